// round 9
// baseline (speedup 1.0000x reference)
#include <cuda_runtime.h>
#include <math.h>

// ---------------- problem constants ----------------
#define B_   2
#define T_   2048
#define E_   1024
#define H_   16
#define HD_  64
#define L_   4
#define V_   32000
#define F_   4096            // 4*E
#define BT_  (B_*T_)         // 4096
#define EPS_ 1e-5f

// ---------------- device scratch (statics: allocation-free at launch) ----------------
__device__ float g_x [BT_*E_];
__device__ float g_h [BT_*E_];
__device__ float g_q [BT_*E_];
__device__ float g_k [BT_*E_];
__device__ float g_v [BT_*E_];
__device__ float g_a [BT_*E_];
__device__ float g_ff[BT_*F_];
__device__ float g_wq[E_*E_];
__device__ float g_wk[E_*E_];
__device__ float g_wv[E_*E_];
__device__ float g_logits[(size_t)BT_ * V_];   // only used if out buffer lacks logits
__device__ float g_rowloss[BT_];
__device__ float g_loss_dummy[1];

// ---------------- embedding ----------------
__global__ void embed_k(const int* __restrict__ idx, const float* __restrict__ tok,
                        const float* __restrict__ pos, float* __restrict__ x) {
    int i = blockIdx.x * blockDim.x + threadIdx.x;
    if (i >= BT_ * E_) return;
    int e  = i & (E_ - 1);
    int bt = i >> 10;            // /E_
    int t  = bt & (T_ - 1);
    x[i] = tok[(size_t)idx[bt] * E_ + e] + pos[(size_t)t * E_ + e];
}

// ---------------- layernorm (one block per row) ----------------
__global__ void ln_k(const float* __restrict__ x, const float* __restrict__ g,
                     const float* __restrict__ b, float* __restrict__ out) {
    __shared__ float red[256];
    int row = blockIdx.x, tid = threadIdx.x;
    const float* xr = x + (size_t)row * E_;
    float s = 0.f;
    for (int e = tid; e < E_; e += 256) s += xr[e];
    red[tid] = s; __syncthreads();
    for (int k = 128; k > 0; k >>= 1) { if (tid < k) red[tid] += red[tid + k]; __syncthreads(); }
    float mean = red[0] * (1.f / E_); __syncthreads();
    float vs = 0.f;
    for (int e = tid; e < E_; e += 256) { float d = xr[e] - mean; vs += d * d; }
    red[tid] = vs; __syncthreads();
    for (int k = 128; k > 0; k >>= 1) { if (tid < k) red[tid] += red[tid + k]; __syncthreads(); }
    float inv = rsqrtf(red[0] * (1.f / E_) + EPS_);
    float* orow = out + (size_t)row * E_;
    for (int e = tid; e < E_; e += 256)
        orow[e] = (xr[e] - mean) * inv * g[e] + b[e];
}

// ---------------- pack Wq/Wk/Wv[l]: [H,E,HD] -> [E, H*HD] ----------------
__global__ void pack_k(const float* __restrict__ Wq, const float* __restrict__ Wk,
                       const float* __restrict__ Wv, int l,
                       float* __restrict__ wq, float* __restrict__ wk, float* __restrict__ wv) {
    int i = blockIdx.x * blockDim.x + threadIdx.x;
    if (i >= E_ * E_) return;
    int e = i >> 10;             // /E_
    int n = i & (E_ - 1);
    int h = n >> 6;              // /HD_
    int d = n & (HD_ - 1);
    size_t src = (((size_t)l * H_ + h) * E_ + e) * HD_ + d;
    wq[i] = Wq[src]; wk[i] = Wk[src]; wv[i] = Wv[src];
}

// ---------------- fp32 GEMM: C[M,N] = A[M,K]*B[K,N] (+bias)(+res)(relu) ----------------
// 128x128 tile, 256 threads, 8x8 per thread (split-tile), BK=8.
// Requires M%128==0, N%128==0, K%8==0 (all shapes here satisfy this).
template<bool BIAS, bool RES, bool RELU>
__global__ void __launch_bounds__(256)
gemm_k(const float* __restrict__ A, const float* __restrict__ Bm,
       const float* __restrict__ bias, const float* __restrict__ res,
       float* __restrict__ C, int M, int N, int K) {
    __shared__ float As[8][132];
    __shared__ float Bs[8][132];
    int tid = threadIdx.x;
    int tx = tid & 15, ty = tid >> 4;
    int n0 = blockIdx.x * 128, m0 = blockIdx.y * 128;

    float acc[8][8];
#pragma unroll
    for (int i = 0; i < 8; i++)
#pragma unroll
        for (int j = 0; j < 8; j++) acc[i][j] = 0.f;

    int a_m = tid >> 1, a_k = (tid & 1) * 4;
    int b_n = (tid & 31) * 4, b_k = tid >> 5;
    const float* Aptr = A  + (size_t)(m0 + a_m) * K + a_k;
    const float* Bptr = Bm + (size_t)b_k * N + n0 + b_n;

    for (int k0 = 0; k0 < K; k0 += 8) {
        float4 av = *(const float4*)(Aptr + k0);
        float4 bv = *(const float4*)(Bptr + (size_t)k0 * N);
        As[a_k + 0][a_m] = av.x;
        As[a_k + 1][a_m] = av.y;
        As[a_k + 2][a_m] = av.z;
        As[a_k + 3][a_m] = av.w;
        *(float4*)&Bs[b_k][b_n] = bv;
        __syncthreads();
#pragma unroll
        for (int kk = 0; kk < 8; kk++) {
            float4 a0 = *(const float4*)&As[kk][ty * 4];
            float4 a1 = *(const float4*)&As[kk][64 + ty * 4];
            float4 b0 = *(const float4*)&Bs[kk][tx * 4];
            float4 b1 = *(const float4*)&Bs[kk][64 + tx * 4];
            float a_[8] = {a0.x, a0.y, a0.z, a0.w, a1.x, a1.y, a1.z, a1.w};
            float b_[8] = {b0.x, b0.y, b0.z, b0.w, b1.x, b1.y, b1.z, b1.w};
#pragma unroll
            for (int i = 0; i < 8; i++)
#pragma unroll
                for (int j = 0; j < 8; j++)
                    acc[i][j] += a_[i] * b_[j];
        }
        __syncthreads();
    }

    int rI[8], cJ[8];
#pragma unroll
    for (int i = 0; i < 4; i++) {
        rI[i] = ty * 4 + i;  rI[i + 4] = 64 + ty * 4 + i;
        cJ[i] = tx * 4 + i;  cJ[i + 4] = 64 + tx * 4 + i;
    }
#pragma unroll
    for (int i = 0; i < 8; i++) {
        size_t rowb = (size_t)(m0 + rI[i]) * N + n0;
#pragma unroll
        for (int j = 0; j < 8; j++) {
            float c = acc[i][j];
            if (BIAS) c += bias[n0 + cJ[j]];
            if (RES)  c += res[rowb + cJ[j]];
            if (RELU) c = fmaxf(c, 0.f);
            C[rowb + cJ[j]] = c;
        }
    }
}

// ---------------- causal attention: one CTA per (b,h,t) query row ----------------
// q,k,v layout: [B,T,H,HD] (i.e. [B,T,E] with n = h*HD+d). out same layout.
__global__ void attn_k(const float* __restrict__ q, const float* __restrict__ k,
                       const float* __restrict__ v, float* __restrict__ out) {
    __shared__ float sc[T_];        // 8 KB
    __shared__ float qs[HD_];
    __shared__ float red[256];
    int t = blockIdx.x, h = blockIdx.y, b = blockIdx.z, tid = threadIdx.x;
    size_t qoff = ((size_t)(b * T_ + t) * H_ + h) * HD_;
    if (tid < HD_) qs[tid] = q[qoff + tid];
    __syncthreads();

    const float4* q4 = (const float4*)qs;
    float lmax = -1e30f;
    for (int s = tid; s <= t; s += 256) {
        const float4* k4 = (const float4*)(k + ((size_t)(b * T_ + s) * H_ + h) * HD_);
        float dot = 0.f;
#pragma unroll
        for (int i = 0; i < HD_ / 4; i++) {
            float4 a = q4[i], c = k4[i];
            dot += a.x * c.x + a.y * c.y + a.z * c.z + a.w * c.w;
        }
        dot *= 0.125f;               // HD^-0.5
        sc[s] = dot;
        lmax = fmaxf(lmax, dot);
    }
    red[tid] = lmax; __syncthreads();
    for (int s2 = 128; s2 > 0; s2 >>= 1) { if (tid < s2) red[tid] = fmaxf(red[tid], red[tid + s2]); __syncthreads(); }
    float mx = red[0]; __syncthreads();

    float lsum = 0.f;
    for (int s = tid; s <= t; s += 256) { float e = expf(sc[s] - mx); sc[s] = e; lsum += e; }
    red[tid] = lsum; __syncthreads();
    for (int s2 = 128; s2 > 0; s2 >>= 1) { if (tid < s2) red[tid] += red[tid + s2]; __syncthreads(); }
    float inv = 1.f / red[0]; __syncthreads();

    int g = tid >> 6, d = tid & 63;
    float acc = 0.f;
    for (int s = g; s <= t; s += 4)
        acc += sc[s] * v[((size_t)(b * T_ + s) * H_ + h) * HD_ + d];
    red[tid] = acc; __syncthreads();
    if (tid < 64) {
        float r = red[tid] + red[tid + 64] + red[tid + 128] + red[tid + 192];
        out[qoff + tid] = r * inv;
    }
}

// ---------------- per-row cross-entropy ----------------
__global__ void rowloss_k(const float* __restrict__ logits, const int* __restrict__ tgt,
                          float* __restrict__ rl) {
    __shared__ float red[256];
    int row = blockIdx.x, tid = threadIdx.x;
    const float* lr = logits + (size_t)row * V_;
    float lmax = -1e30f;
    for (int i = tid; i < V_; i += 256) lmax = fmaxf(lmax, lr[i]);
    red[tid] = lmax; __syncthreads();
    for (int k = 128; k > 0; k >>= 1) { if (tid < k) red[tid] = fmaxf(red[tid], red[tid + k]); __syncthreads(); }
    float mx = red[0]; __syncthreads();
    float s = 0.f;
    for (int i = tid; i < V_; i += 256) s += expf(lr[i] - mx);
    red[tid] = s; __syncthreads();
    for (int k = 128; k > 0; k >>= 1) { if (tid < k) red[tid] += red[tid + k]; __syncthreads(); }
    if (tid == 0) rl[row] = -(lr[tgt[row]] - mx - logf(red[0]));
}

__global__ void finloss_k(const float* __restrict__ rl, float* __restrict__ dst) {
    __shared__ float red[256];
    int tid = threadIdx.x;
    float s = 0.f;
    for (int i = tid; i < BT_; i += 256) s += rl[i];
    red[tid] = s; __syncthreads();
    for (int k = 128; k > 0; k >>= 1) { if (tid < k) red[tid] += red[tid + k]; __syncthreads(); }
    if (tid == 0) dst[0] = red[0] * (1.f / BT_);
}

// ---------------- launch ----------------
extern "C" void kernel_launch(void* const* d_in, const int* in_sizes, int n_in,
                              void* d_out, int out_size) {
    const int*   idx     = (const int*)  d_in[0];
    const int*   targets = (const int*)  d_in[1];
    const float* tok     = (const float*)d_in[2];
    const float* pos     = (const float*)d_in[3];
    const float* Wq      = (const float*)d_in[4];
    const float* Wk      = (const float*)d_in[5];
    const float* Wv      = (const float*)d_in[6];
    const float* Wproj   = (const float*)d_in[7];
    const float* bproj   = (const float*)d_in[8];
    const float* ln1g    = (const float*)d_in[9];
    const float* ln1b    = (const float*)d_in[10];
    const float* ln2g    = (const float*)d_in[11];
    const float* ln2b    = (const float*)d_in[12];
    const float* W1      = (const float*)d_in[13];
    const float* b1      = (const float*)d_in[14];
    const float* W2      = (const float*)d_in[15];
    const float* b2      = (const float*)d_in[16];
    const float* lnfg    = (const float*)d_in[17];
    const float* lnfb    = (const float*)d_in[18];
    const float* Whead   = (const float*)d_in[19];
    const float* bhead   = (const float*)d_in[20];

    float *x, *h, *q, *k, *v, *a, *ff, *wq, *wk, *wv, *lgs, *rl, *dummy;
    cudaGetSymbolAddress((void**)&x,  g_x);
    cudaGetSymbolAddress((void**)&h,  g_h);
    cudaGetSymbolAddress((void**)&q,  g_q);
    cudaGetSymbolAddress((void**)&k,  g_k);
    cudaGetSymbolAddress((void**)&v,  g_v);
    cudaGetSymbolAddress((void**)&a,  g_a);
    cudaGetSymbolAddress((void**)&ff, g_ff);
    cudaGetSymbolAddress((void**)&wq, g_wq);
    cudaGetSymbolAddress((void**)&wk, g_wk);
    cudaGetSymbolAddress((void**)&wv, g_wv);
    cudaGetSymbolAddress((void**)&lgs, g_logits);
    cudaGetSymbolAddress((void**)&rl, g_rowloss);
    cudaGetSymbolAddress((void**)&dummy, g_loss_dummy);

    float* out = (float*)d_out;
    const long long BTV = (long long)BT_ * V_;
    float* logits   = ((long long)out_size >= BTV) ? out : lgs;
    float* loss_dst = ((long long)out_size == BTV + 1) ? (out + BTV)
                    : (((long long)out_size < BTV) ? out : dummy);

    embed_k<<<(BT_ * E_ + 255) / 256, 256>>>(idx, tok, pos, x);

    for (int l = 0; l < L_; l++) {
        ln_k<<<BT_, 256>>>(x, ln1g + l * E_, ln1b + l * E_, h);
        pack_k<<<(E_ * E_ + 255) / 256, 256>>>(Wq, Wk, Wv, l, wq, wk, wv);

        dim3 gE(E_ / 128, BT_ / 128);
        gemm_k<false, false, false><<<gE, 256>>>(h, wq, nullptr, nullptr, q, BT_, E_, E_);
        gemm_k<false, false, false><<<gE, 256>>>(h, wk, nullptr, nullptr, k, BT_, E_, E_);
        gemm_k<false, false, false><<<gE, 256>>>(h, wv, nullptr, nullptr, v, BT_, E_, E_);

        attn_k<<<dim3(T_, H_, B_), 256>>>(q, k, v, a);

        gemm_k<true, true, false><<<gE, 256>>>(a, Wproj + (size_t)l * E_ * E_, bproj + l * E_,
                                               x, x, BT_, E_, E_);

        ln_k<<<BT_, 256>>>(x, ln2g + l * E_, ln2b + l * E_, h);

        gemm_k<true, false, true><<<dim3(F_ / 128, BT_ / 128), 256>>>(
            h, W1 + (size_t)l * E_ * F_, b1 + l * F_, nullptr, ff, BT_, F_, E_);

        gemm_k<true, true, false><<<gE, 256>>>(
            ff, W2 + (size_t)l * F_ * E_, b2 + l * E_, x, x, BT_, E_, F_);
    }

    ln_k<<<BT_, 256>>>(x, lnfg, lnfb, h);

    gemm_k<true, false, false><<<dim3(V_ / 128, BT_ / 128), 256>>>(
        h, Whead, bhead, nullptr, logits, BT_, V_, E_);

    rowloss_k<<<BT_, 256>>>(logits, targets, rl);
    finloss_k<<<1, 256>>>(rl, loss_dst);
}

// round 10
// speedup vs baseline: 1.0007x; 1.0007x over previous
#include <cuda_runtime.h>
#include <math.h>

// ---------------- problem constants ----------------
#define B_   2
#define T_   2048
#define E_   1024
#define H_   16
#define HD_  64
#define L_   4
#define V_   32000
#define F_   4096            // 4*E
#define BT_  (B_*T_)         // 4096
#define EPS_ 1e-5f

// ---------------- device scratch (statics: allocation-free at launch) ----------------
__device__ float g_x [BT_*E_];
__device__ float g_h [BT_*E_];
__device__ float g_q [BT_*E_];
__device__ float g_k [BT_*E_];
__device__ float g_v [BT_*E_];
__device__ float g_a [BT_*E_];
__device__ float g_ff[BT_*F_];
__device__ float g_wq[E_*E_];
__device__ float g_wk[E_*E_];
__device__ float g_wv[E_*E_];
__device__ float g_logits[(size_t)BT_ * V_];   // only used if out buffer lacks logits
__device__ float g_rowloss[BT_];
__device__ float g_loss_dummy[1];

// ---------------- embedding ----------------
__global__ void embed_k(const int* __restrict__ idx, const float* __restrict__ tok,
                        const float* __restrict__ pos, float* __restrict__ x) {
    int i = blockIdx.x * blockDim.x + threadIdx.x;
    if (i >= BT_ * E_) return;
    int e  = i & (E_ - 1);
    int bt = i >> 10;            // /E_
    int t  = bt & (T_ - 1);
    x[i] = tok[(size_t)idx[bt] * E_ + e] + pos[(size_t)t * E_ + e];
}

// ---------------- layernorm (one block per row) ----------------
__global__ void ln_k(const float* __restrict__ x, const float* __restrict__ g,
                     const float* __restrict__ b, float* __restrict__ out) {
    __shared__ float red[256];
    int row = blockIdx.x, tid = threadIdx.x;
    const float* xr = x + (size_t)row * E_;
    float s = 0.f;
    for (int e = tid; e < E_; e += 256) s += xr[e];
    red[tid] = s; __syncthreads();
    for (int k = 128; k > 0; k >>= 1) { if (tid < k) red[tid] += red[tid + k]; __syncthreads(); }
    float mean = red[0] * (1.f / E_); __syncthreads();
    float vs = 0.f;
    for (int e = tid; e < E_; e += 256) { float d = xr[e] - mean; vs += d * d; }
    red[tid] = vs; __syncthreads();
    for (int k = 128; k > 0; k >>= 1) { if (tid < k) red[tid] += red[tid + k]; __syncthreads(); }
    float inv = rsqrtf(red[0] * (1.f / E_) + EPS_);
    float* orow = out + (size_t)row * E_;
    for (int e = tid; e < E_; e += 256)
        orow[e] = (xr[e] - mean) * inv * g[e] + b[e];
}

// ---------------- pack Wq/Wk/Wv[l]: [H,E,HD] -> [E, H*HD] ----------------
__global__ void pack_k(const float* __restrict__ Wq, const float* __restrict__ Wk,
                       const float* __restrict__ Wv, int l,
                       float* __restrict__ wq, float* __restrict__ wk, float* __restrict__ wv) {
    int i = blockIdx.x * blockDim.x + threadIdx.x;
    if (i >= E_ * E_) return;
    int e = i >> 10;             // /E_
    int n = i & (E_ - 1);
    int h = n >> 6;              // /HD_
    int d = n & (HD_ - 1);
    size_t src = (((size_t)l * H_ + h) * E_ + e) * HD_ + d;
    wq[i] = Wq[src]; wk[i] = Wk[src]; wv[i] = Wv[src];
}

// ---------------- fp32 GEMM: C[M,N] = A[M,K]*B[K,N] (+bias)(+res)(relu) ----------------
// 128x128 tile, 256 threads, 8x8 per thread (split-tile), BK=8.
// Requires M%128==0, N%128==0, K%8==0 (all shapes here satisfy this).
template<bool BIAS, bool RES, bool RELU>
__global__ void __launch_bounds__(256)
gemm_k(const float* __restrict__ A, const float* __restrict__ Bm,
       const float* __restrict__ bias, const float* __restrict__ res,
       float* __restrict__ C, int M, int N, int K) {
    __shared__ float As[8][132];
    __shared__ float Bs[8][132];
    int tid = threadIdx.x;
    int tx = tid & 15, ty = tid >> 4;
    int n0 = blockIdx.x * 128, m0 = blockIdx.y * 128;

    float acc[8][8];
#pragma unroll
    for (int i = 0; i < 8; i++)
#pragma unroll
        for (int j = 0; j < 8; j++) acc[i][j] = 0.f;

    int a_m = tid >> 1, a_k = (tid & 1) * 4;
    int b_n = (tid & 31) * 4, b_k = tid >> 5;
    const float* Aptr = A  + (size_t)(m0 + a_m) * K + a_k;
    const float* Bptr = Bm + (size_t)b_k * N + n0 + b_n;

    for (int k0 = 0; k0 < K; k0 += 8) {
        float4 av = *(const float4*)(Aptr + k0);
        float4 bv = *(const float4*)(Bptr + (size_t)k0 * N);
        As[a_k + 0][a_m] = av.x;
        As[a_k + 1][a_m] = av.y;
        As[a_k + 2][a_m] = av.z;
        As[a_k + 3][a_m] = av.w;
        *(float4*)&Bs[b_k][b_n] = bv;
        __syncthreads();
#pragma unroll
        for (int kk = 0; kk < 8; kk++) {
            float4 a0 = *(const float4*)&As[kk][ty * 4];
            float4 a1 = *(const float4*)&As[kk][64 + ty * 4];
            float4 b0 = *(const float4*)&Bs[kk][tx * 4];
            float4 b1 = *(const float4*)&Bs[kk][64 + tx * 4];
            float a_[8] = {a0.x, a0.y, a0.z, a0.w, a1.x, a1.y, a1.z, a1.w};
            float b_[8] = {b0.x, b0.y, b0.z, b0.w, b1.x, b1.y, b1.z, b1.w};
#pragma unroll
            for (int i = 0; i < 8; i++)
#pragma unroll
                for (int j = 0; j < 8; j++)
                    acc[i][j] += a_[i] * b_[j];
        }
        __syncthreads();
    }

    int rI[8], cJ[8];
#pragma unroll
    for (int i = 0; i < 4; i++) {
        rI[i] = ty * 4 + i;  rI[i + 4] = 64 + ty * 4 + i;
        cJ[i] = tx * 4 + i;  cJ[i + 4] = 64 + tx * 4 + i;
    }
#pragma unroll
    for (int i = 0; i < 8; i++) {
        size_t rowb = (size_t)(m0 + rI[i]) * N + n0;
#pragma unroll
        for (int j = 0; j < 8; j++) {
            float c = acc[i][j];
            if (BIAS) c += bias[n0 + cJ[j]];
            if (RES)  c += res[rowb + cJ[j]];
            if (RELU) c = fmaxf(c, 0.f);
            C[rowb + cJ[j]] = c;
        }
    }
}

// ---------------- causal attention: one CTA per (b,h,t) query row ----------------
// q,k,v layout: [B,T,H,HD] (i.e. [B,T,E] with n = h*HD+d). out same layout.
__global__ void attn_k(const float* __restrict__ q, const float* __restrict__ k,
                       const float* __restrict__ v, float* __restrict__ out) {
    __shared__ float sc[T_];        // 8 KB
    __shared__ float qs[HD_];
    __shared__ float red[256];
    int t = blockIdx.x, h = blockIdx.y, b = blockIdx.z, tid = threadIdx.x;
    size_t qoff = ((size_t)(b * T_ + t) * H_ + h) * HD_;
    if (tid < HD_) qs[tid] = q[qoff + tid];
    __syncthreads();

    const float4* q4 = (const float4*)qs;
    float lmax = -1e30f;
    for (int s = tid; s <= t; s += 256) {
        const float4* k4 = (const float4*)(k + ((size_t)(b * T_ + s) * H_ + h) * HD_);
        float dot = 0.f;
#pragma unroll
        for (int i = 0; i < HD_ / 4; i++) {
            float4 a = q4[i], c = k4[i];
            dot += a.x * c.x + a.y * c.y + a.z * c.z + a.w * c.w;
        }
        dot *= 0.125f;               // HD^-0.5
        sc[s] = dot;
        lmax = fmaxf(lmax, dot);
    }
    red[tid] = lmax; __syncthreads();
    for (int s2 = 128; s2 > 0; s2 >>= 1) { if (tid < s2) red[tid] = fmaxf(red[tid], red[tid + s2]); __syncthreads(); }
    float mx = red[0]; __syncthreads();

    float lsum = 0.f;
    for (int s = tid; s <= t; s += 256) { float e = expf(sc[s] - mx); sc[s] = e; lsum += e; }
    red[tid] = lsum; __syncthreads();
    for (int s2 = 128; s2 > 0; s2 >>= 1) { if (tid < s2) red[tid] += red[tid + s2]; __syncthreads(); }
    float inv = 1.f / red[0]; __syncthreads();

    int g = tid >> 6, d = tid & 63;
    float acc = 0.f;
    for (int s = g; s <= t; s += 4)
        acc += sc[s] * v[((size_t)(b * T_ + s) * H_ + h) * HD_ + d];
    red[tid] = acc; __syncthreads();
    if (tid < 64) {
        float r = red[tid] + red[tid + 64] + red[tid + 128] + red[tid + 192];
        out[qoff + tid] = r * inv;
    }
}

// ---------------- per-row cross-entropy ----------------
__global__ void rowloss_k(const float* __restrict__ logits, const int* __restrict__ tgt,
                          float* __restrict__ rl) {
    __shared__ float red[256];
    int row = blockIdx.x, tid = threadIdx.x;
    const float* lr = logits + (size_t)row * V_;
    float lmax = -1e30f;
    for (int i = tid; i < V_; i += 256) lmax = fmaxf(lmax, lr[i]);
    red[tid] = lmax; __syncthreads();
    for (int k = 128; k > 0; k >>= 1) { if (tid < k) red[tid] = fmaxf(red[tid], red[tid + k]); __syncthreads(); }
    float mx = red[0]; __syncthreads();
    float s = 0.f;
    for (int i = tid; i < V_; i += 256) s += expf(lr[i] - mx);
    red[tid] = s; __syncthreads();
    for (int k = 128; k > 0; k >>= 1) { if (tid < k) red[tid] += red[tid + k]; __syncthreads(); }
    if (tid == 0) rl[row] = -(lr[tgt[row]] - mx - logf(red[0]));
}

__global__ void finloss_k(const float* __restrict__ rl, float* __restrict__ dst) {
    __shared__ float red[256];
    int tid = threadIdx.x;
    float s = 0.f;
    for (int i = tid; i < BT_; i += 256) s += rl[i];
    red[tid] = s; __syncthreads();
    for (int k = 128; k > 0; k >>= 1) { if (tid < k) red[tid] += red[tid + k]; __syncthreads(); }
    if (tid == 0) dst[0] = red[0] * (1.f / BT_);
}

// ---------------- launch ----------------
extern "C" void kernel_launch(void* const* d_in, const int* in_sizes, int n_in,
                              void* d_out, int out_size) {
    const int*   idx     = (const int*)  d_in[0];
    const int*   targets = (const int*)  d_in[1];
    const float* tok     = (const float*)d_in[2];
    const float* pos     = (const float*)d_in[3];
    const float* Wq      = (const float*)d_in[4];
    const float* Wk      = (const float*)d_in[5];
    const float* Wv      = (const float*)d_in[6];
    const float* Wproj   = (const float*)d_in[7];
    const float* bproj   = (const float*)d_in[8];
    const float* ln1g    = (const float*)d_in[9];
    const float* ln1b    = (const float*)d_in[10];
    const float* ln2g    = (const float*)d_in[11];
    const float* ln2b    = (const float*)d_in[12];
    const float* W1      = (const float*)d_in[13];
    const float* b1      = (const float*)d_in[14];
    const float* W2      = (const float*)d_in[15];
    const float* b2      = (const float*)d_in[16];
    const float* lnfg    = (const float*)d_in[17];
    const float* lnfb    = (const float*)d_in[18];
    const float* Whead   = (const float*)d_in[19];
    const float* bhead   = (const float*)d_in[20];

    float *x, *h, *q, *k, *v, *a, *ff, *wq, *wk, *wv, *lgs, *rl, *dummy;
    cudaGetSymbolAddress((void**)&x,  g_x);
    cudaGetSymbolAddress((void**)&h,  g_h);
    cudaGetSymbolAddress((void**)&q,  g_q);
    cudaGetSymbolAddress((void**)&k,  g_k);
    cudaGetSymbolAddress((void**)&v,  g_v);
    cudaGetSymbolAddress((void**)&a,  g_a);
    cudaGetSymbolAddress((void**)&ff, g_ff);
    cudaGetSymbolAddress((void**)&wq, g_wq);
    cudaGetSymbolAddress((void**)&wk, g_wk);
    cudaGetSymbolAddress((void**)&wv, g_wv);
    cudaGetSymbolAddress((void**)&lgs, g_logits);
    cudaGetSymbolAddress((void**)&rl, g_rowloss);
    cudaGetSymbolAddress((void**)&dummy, g_loss_dummy);

    float* out = (float*)d_out;
    const long long BTV = (long long)BT_ * V_;
    float* logits   = ((long long)out_size >= BTV) ? out : lgs;
    float* loss_dst = ((long long)out_size == BTV + 1) ? (out + BTV)
                    : (((long long)out_size < BTV) ? out : dummy);

    embed_k<<<(BT_ * E_ + 255) / 256, 256>>>(idx, tok, pos, x);

    for (int l = 0; l < L_; l++) {
        ln_k<<<BT_, 256>>>(x, ln1g + l * E_, ln1b + l * E_, h);
        pack_k<<<(E_ * E_ + 255) / 256, 256>>>(Wq, Wk, Wv, l, wq, wk, wv);

        dim3 gE(E_ / 128, BT_ / 128);
        gemm_k<false, false, false><<<gE, 256>>>(h, wq, nullptr, nullptr, q, BT_, E_, E_);
        gemm_k<false, false, false><<<gE, 256>>>(h, wk, nullptr, nullptr, k, BT_, E_, E_);
        gemm_k<false, false, false><<<gE, 256>>>(h, wv, nullptr, nullptr, v, BT_, E_, E_);

        attn_k<<<dim3(T_, H_, B_), 256>>>(q, k, v, a);

        gemm_k<true, true, false><<<gE, 256>>>(a, Wproj + (size_t)l * E_ * E_, bproj + l * E_,
                                               x, x, BT_, E_, E_);

        ln_k<<<BT_, 256>>>(x, ln2g + l * E_, ln2b + l * E_, h);

        gemm_k<true, false, true><<<dim3(F_ / 128, BT_ / 128), 256>>>(
            h, W1 + (size_t)l * E_ * F_, b1 + l * F_, nullptr, ff, BT_, F_, E_);

        gemm_k<true, true, false><<<gE, 256>>>(
            ff, W2 + (size_t)l * F_ * E_, b2 + l * E_, x, x, BT_, E_, F_);
    }

    ln_k<<<BT_, 256>>>(x, lnfg, lnfb, h);

    gemm_k<true, false, false><<<dim3(V_ / 128, BT_ / 128), 256>>>(
        h, Whead, bhead, nullptr, logits, BT_, V_, E_);

    rowloss_k<<<BT_, 256>>>(logits, targets, rl);
    finloss_k<<<1, 256>>>(rl, loss_dst);
}